// round 8
// baseline (speedup 1.0000x reference)
#include <cuda_runtime.h>
#include <cuda_bf16.h>
#include <cstddef>
#include <cstdint>

// LIF activation over time axis.
// x: [B=64, T=500, C=1024] fp32; w_input, w_leak: device scalars.
// out: spikes [B, T, C] fp32 (0.0/1.0).
//
// R7 -> R8: TMA pipeline confirmed (DRAM 58->72.5%). Remaining loss was
// grid=128 leaving 20/148 SMs idle (13.5%). Re-grain: 128 channels per
// block -> grid=1024, block=64 (32 compute threads * float4 + producer).
// ~7 CTAs/SM resident -> 1.2% imbalance. TMA copies 512B each; in-flight
// ~140KB/SM via TMA (vs ~16KB needed). Pipeline identical to R7 otherwise.

#define LIF_B 64
#define LIF_T 500
#define LIF_C 1024
#define LIF_CH 128                       // channels per block
#define LIF_D 10                         // timesteps per stage
#define LIF_NS 5                         // pipeline stages
#define LIF_NCHUNK (LIF_T / LIF_D)       // 50
#define ROW_BYTES (LIF_CH * 4)           // 512
#define STAGE_BYTES (LIF_D * ROW_BYTES)  // 5120
#define SMEM_BYTES (LIF_NS * STAGE_BYTES)
#define NTHREADS 64
#define NCOMPUTE 32

__device__ __forceinline__ uint32_t smem_u32(const void* p) {
    return (uint32_t)__cvta_generic_to_shared(p);
}

__device__ __forceinline__ void mbar_init(uint32_t bar, uint32_t count) {
    asm volatile("mbarrier.init.shared.b64 [%0], %1;" :: "r"(bar), "r"(count) : "memory");
}
__device__ __forceinline__ void mbar_arrive(uint32_t bar) {
    asm volatile("mbarrier.arrive.shared.b64 _, [%0];" :: "r"(bar) : "memory");
}
__device__ __forceinline__ void mbar_expect_tx(uint32_t bar, uint32_t bytes) {
    asm volatile("mbarrier.arrive.expect_tx.shared.b64 _, [%0], %1;"
                 :: "r"(bar), "r"(bytes) : "memory");
}
__device__ __forceinline__ void mbar_wait(uint32_t bar, uint32_t parity) {
    asm volatile(
        "{\n\t"
        ".reg .pred P;\n\t"
        "WAIT_%=:\n\t"
        "mbarrier.try_wait.parity.acquire.cta.shared::cta.b64 P, [%0], %1, 0x989680;\n\t"
        "@!P bra WAIT_%=;\n\t"
        "}"
        :: "r"(bar), "r"(parity) : "memory");
}
__device__ __forceinline__ void bulk_g2s(uint32_t dst, const void* src,
                                         uint32_t bytes, uint32_t bar) {
    asm volatile(
        "cp.async.bulk.shared::cta.global.mbarrier::complete_tx::bytes [%0], [%1], %2, [%3];"
        :: "r"(dst), "l"(src), "r"(bytes), "r"(bar) : "memory");
}

__global__ __launch_bounds__(NTHREADS) void lif_kernel(
    const float* __restrict__ x,
    const float* __restrict__ w_input_p,
    const float* __restrict__ w_leak_p,
    float* __restrict__ out)
{
    extern __shared__ float sdata[];                    // LIF_NS stages of [D][128] floats
    __shared__ __align__(8) uint64_t mbar[2 * LIF_NS];  // full[0..NS), empty[0..NS)

    const int tid = threadIdx.x;
    const uint32_t sbase  = smem_u32(sdata);
    const uint32_t full0  = smem_u32(&mbar[0]);
    const uint32_t empty0 = smem_u32(&mbar[LIF_NS]);

    if (tid == 0) {
        #pragma unroll
        for (int s = 0; s < LIF_NS; s++) {
            mbar_init(full0  + 8u * s, 1);         // producer expect_tx arrival
            mbar_init(empty0 + 8u * s, NCOMPUTE);  // all compute threads arrive
        }
    }
    __syncthreads();

    const int blk    = blockIdx.x;      // 0..1023
    const int b      = blk >> 3;        // batch
    const int cchunk = blk & 7;         // which 128-channel chunk
    const size_t gbase = (size_t)b * LIF_T * LIF_C + (size_t)cchunk * LIF_CH;

    if (tid >= NCOMPUTE) {
        // ---------------- producer warp (one thread drives TMA) ----------------
        if (tid != NCOMPUTE) return;
        const char* src0 = (const char*)(x + gbase);
        int ph = 1;                     // empty barriers: first pass must not block
        #pragma unroll 1
        for (int k = 0; k < LIF_NCHUNK; k++) {
            const int s = k % LIF_NS;
            mbar_wait(empty0 + 8u * s, (uint32_t)ph);
            mbar_expect_tx(full0 + 8u * s, STAGE_BYTES);
            const char* src = src0 + (size_t)k * LIF_D * LIF_C * 4;
            #pragma unroll
            for (int j = 0; j < LIF_D; j++)
                bulk_g2s(sbase + (uint32_t)(s * LIF_D + j) * ROW_BYTES,
                         src + (size_t)j * LIF_C * 4,
                         ROW_BYTES, full0 + 8u * s);
            if (s == LIF_NS - 1) ph ^= 1;
        }
        return;
    }

    // ---------------- compute threads (32, float4 each) ----------------
    const float wi   = *w_input_p;
    const float keep = 1.0f - *w_leak_p;

    float* orow = out + gbase;          // + t*C + tid*4 per step
    float Vm0 = 0.0f, Vm1 = 0.0f, Vm2 = 0.0f, Vm3 = 0.0f;
    int ph = 0;

    #pragma unroll 1
    for (int k = 0; k < LIF_NCHUNK; k++) {
        const int s = k % LIF_NS;
        mbar_wait(full0 + 8u * s, (uint32_t)ph);

        const float4* srow = (const float4*)(sdata + (size_t)s * LIF_D * LIF_CH) + tid;
        #pragma unroll
        for (int j = 0; j < LIF_D; j++) {
            const float4 xv = srow[(size_t)j * (LIF_CH / 4)];
            const float vk0 = (Vm0 < 1.0f) ? Vm0 : 0.0f;   // Vm * step(1-Vm)
            const float vk1 = (Vm1 < 1.0f) ? Vm1 : 0.0f;
            const float vk2 = (Vm2 < 1.0f) ? Vm2 : 0.0f;
            const float vk3 = (Vm3 < 1.0f) ? Vm3 : 0.0f;
            Vm0 = fmaxf(fmaf(keep, vk0, wi * xv.x), 0.0f);
            Vm1 = fmaxf(fmaf(keep, vk1, wi * xv.y), 0.0f);
            Vm2 = fmaxf(fmaf(keep, vk2, wi * xv.z), 0.0f);
            Vm3 = fmaxf(fmaf(keep, vk3, wi * xv.w), 0.0f);
            float4 sp;
            sp.x = (Vm0 > 1.0f) ? 1.0f : 0.0f;
            sp.y = (Vm1 > 1.0f) ? 1.0f : 0.0f;
            sp.z = (Vm2 > 1.0f) ? 1.0f : 0.0f;
            sp.w = (Vm3 > 1.0f) ? 1.0f : 0.0f;
            *(float4*)(orow + (size_t)(k * LIF_D + j) * LIF_C + tid * 4) = sp;
        }

        mbar_arrive(empty0 + 8u * s);
        if (s == LIF_NS - 1) ph ^= 1;
    }
}

extern "C" void kernel_launch(void* const* d_in, const int* in_sizes, int n_in,
                              void* d_out, int out_size) {
    const float* x        = (const float*)d_in[0];
    const float* w_input  = (const float*)d_in[1];
    const float* w_leak   = (const float*)d_in[2];
    float* out            = (float*)d_out;

    cudaFuncSetAttribute(lif_kernel,
                         cudaFuncAttributeMaxDynamicSharedMemorySize, SMEM_BYTES);

    lif_kernel<<<LIF_B * 8, NTHREADS, SMEM_BYTES>>>(x, w_input, w_leak, out);
}

// round 9
// speedup vs baseline: 1.0071x; 1.0071x over previous
#include <cuda_runtime.h>
#include <cuda_bf16.h>
#include <cstddef>
#include <cstdint>

// LIF activation over time axis.
// x: [B=64, T=500, C=1024] fp32; w_input, w_leak: device scalars.
// out: spikes [B, T, C] fp32 (0.0/1.0).
//
// R8 -> R9: R8's "1024 blocks" was actually 512 (64*8) -> per-SM max bytes
// identical to R7 (1.024MB), so no balance win, only extra overhead.
// This round truly hits 1024 blocks: 64 channels/block (16 chunks/row).
// Per-SM max = 7 * 0.128MB = 0.896MB vs 0.886MB ideal (1.2% over).
// Block=64: warp0 = 32 compute threads (float2), warp1 thread drives TMA.
// 5-stage pipeline, 10 timesteps/stage (2.56KB), 12.8KB smem, 7 CTAs/SM.

#define LIF_B 64
#define LIF_T 500
#define LIF_C 1024
#define LIF_CH 64                        // channels per block
#define LIF_NCHK 16                      // chunks per row (C / CH)
#define LIF_D 10                         // timesteps per stage
#define LIF_NS 5                         // pipeline stages
#define LIF_NCHUNK (LIF_T / LIF_D)       // 50
#define ROW_BYTES (LIF_CH * 4)           // 256
#define STAGE_BYTES (LIF_D * ROW_BYTES)  // 2560
#define SMEM_BYTES (LIF_NS * STAGE_BYTES)
#define NTHREADS 64
#define NCOMPUTE 32

__device__ __forceinline__ uint32_t smem_u32(const void* p) {
    return (uint32_t)__cvta_generic_to_shared(p);
}

__device__ __forceinline__ void mbar_init(uint32_t bar, uint32_t count) {
    asm volatile("mbarrier.init.shared.b64 [%0], %1;" :: "r"(bar), "r"(count) : "memory");
}
__device__ __forceinline__ void mbar_arrive(uint32_t bar) {
    asm volatile("mbarrier.arrive.shared.b64 _, [%0];" :: "r"(bar) : "memory");
}
__device__ __forceinline__ void mbar_expect_tx(uint32_t bar, uint32_t bytes) {
    asm volatile("mbarrier.arrive.expect_tx.shared.b64 _, [%0], %1;"
                 :: "r"(bar), "r"(bytes) : "memory");
}
__device__ __forceinline__ void mbar_wait(uint32_t bar, uint32_t parity) {
    asm volatile(
        "{\n\t"
        ".reg .pred P;\n\t"
        "WAIT_%=:\n\t"
        "mbarrier.try_wait.parity.acquire.cta.shared::cta.b64 P, [%0], %1, 0x989680;\n\t"
        "@!P bra WAIT_%=;\n\t"
        "}"
        :: "r"(bar), "r"(parity) : "memory");
}
__device__ __forceinline__ void bulk_g2s(uint32_t dst, const void* src,
                                         uint32_t bytes, uint32_t bar) {
    asm volatile(
        "cp.async.bulk.shared::cta.global.mbarrier::complete_tx::bytes [%0], [%1], %2, [%3];"
        :: "r"(dst), "l"(src), "r"(bytes), "r"(bar) : "memory");
}

__global__ __launch_bounds__(NTHREADS) void lif_kernel(
    const float* __restrict__ x,
    const float* __restrict__ w_input_p,
    const float* __restrict__ w_leak_p,
    float* __restrict__ out)
{
    extern __shared__ float sdata[];                    // LIF_NS stages of [D][64] floats
    __shared__ __align__(8) uint64_t mbar[2 * LIF_NS];  // full[0..NS), empty[0..NS)

    const int tid = threadIdx.x;
    const uint32_t sbase  = smem_u32(sdata);
    const uint32_t full0  = smem_u32(&mbar[0]);
    const uint32_t empty0 = smem_u32(&mbar[LIF_NS]);

    if (tid == 0) {
        #pragma unroll
        for (int s = 0; s < LIF_NS; s++) {
            mbar_init(full0  + 8u * s, 1);         // producer expect_tx arrival
            mbar_init(empty0 + 8u * s, NCOMPUTE);  // all compute threads arrive
        }
    }
    __syncthreads();

    const int blk    = blockIdx.x;       // 0..1023
    const int b      = blk >> 4;         // batch
    const int cchunk = blk & (LIF_NCHK - 1);
    const size_t gbase = (size_t)b * LIF_T * LIF_C + (size_t)cchunk * LIF_CH;

    if (tid >= NCOMPUTE) {
        // ---------------- producer (one thread drives TMA) ----------------
        if (tid != NCOMPUTE) return;
        const char* src0 = (const char*)(x + gbase);
        int ph = 1;                      // empty barriers: first pass must not block
        #pragma unroll 1
        for (int k = 0; k < LIF_NCHUNK; k++) {
            const int s = k % LIF_NS;
            mbar_wait(empty0 + 8u * s, (uint32_t)ph);
            mbar_expect_tx(full0 + 8u * s, STAGE_BYTES);
            const char* src = src0 + (size_t)k * LIF_D * LIF_C * 4;
            #pragma unroll
            for (int j = 0; j < LIF_D; j++)
                bulk_g2s(sbase + (uint32_t)(s * LIF_D + j) * ROW_BYTES,
                         src + (size_t)j * LIF_C * 4,
                         ROW_BYTES, full0 + 8u * s);
            if (s == LIF_NS - 1) ph ^= 1;
        }
        return;
    }

    // ---------------- compute threads (32, float2 each) ----------------
    const float wi   = *w_input_p;
    const float keep = 1.0f - *w_leak_p;

    float* optr = out + gbase + (size_t)tid * 2;   // walks forward by C per step
    float Vm0 = 0.0f, Vm1 = 0.0f;
    int ph = 0;

    #pragma unroll 1
    for (int k = 0; k < LIF_NCHUNK; k++) {
        const int s = k % LIF_NS;
        mbar_wait(full0 + 8u * s, (uint32_t)ph);

        const float2* srow = (const float2*)(sdata + (size_t)s * LIF_D * LIF_CH) + tid;
        #pragma unroll
        for (int j = 0; j < LIF_D; j++) {
            const float2 xv = srow[(size_t)j * (LIF_CH / 2)];
            const float vk0 = (Vm0 < 1.0f) ? Vm0 : 0.0f;   // Vm * step(1-Vm)
            const float vk1 = (Vm1 < 1.0f) ? Vm1 : 0.0f;
            Vm0 = fmaxf(fmaf(keep, vk0, wi * xv.x), 0.0f);
            Vm1 = fmaxf(fmaf(keep, vk1, wi * xv.y), 0.0f);
            float2 sp;
            sp.x = (Vm0 > 1.0f) ? 1.0f : 0.0f;
            sp.y = (Vm1 > 1.0f) ? 1.0f : 0.0f;
            *reinterpret_cast<float2*>(optr) = sp;
            optr += LIF_C;
        }

        mbar_arrive(empty0 + 8u * s);
        if (s == LIF_NS - 1) ph ^= 1;
    }
}

extern "C" void kernel_launch(void* const* d_in, const int* in_sizes, int n_in,
                              void* d_out, int out_size) {
    const float* x        = (const float*)d_in[0];
    const float* w_input  = (const float*)d_in[1];
    const float* w_leak   = (const float*)d_in[2];
    float* out            = (float*)d_out;

    cudaFuncSetAttribute(lif_kernel,
                         cudaFuncAttributeMaxDynamicSharedMemorySize, SMEM_BYTES);

    lif_kernel<<<LIF_B * LIF_NCHK, NTHREADS, SMEM_BYTES>>>(x, w_input, w_leak, out);
}

// round 10
// speedup vs baseline: 1.0700x; 1.0624x over previous
#include <cuda_runtime.h>
#include <cuda_bf16.h>
#include <cstddef>
#include <cstdint>

// LIF activation over time axis.
// x: [B=64, T=500, C=1024] fp32; w_input, w_leak: device scalars.
// out: spikes [B, T, C] fp32 (0.0/1.0).
//
// R9 -> R10: balanced-grid experiment (R9) was SLOWER than 128 big blocks
// (R7) -> SM-side balance is not the binder. Totals show we are end-to-end
// DRAM bound at ~5.6 TB/s effective (262 MB / 47us harness dur). Cause
// hypothesis: single-use read stream allocates in L2, evicting dirty write
// lines in scattered order -> poor DRAM row locality + turnaround loss.
// Fix (R7 shape unchanged otherwise):
//   * TMA bulk reads with L2::cache_hint evict_first (don't pollute L2)
//   * spike stores via st.global.cs (evict-first, drain in written order)

#define LIF_B 64
#define LIF_T 500
#define LIF_C 1024
#define LIF_HALF 512                     // channels per block
#define LIF_D 10                         // timesteps per stage
#define LIF_NS 5                         // pipeline stages
#define LIF_NCHUNK (LIF_T / LIF_D)       // 50
#define ROW_BYTES (LIF_HALF * 4)         // 2048
#define STAGE_BYTES (LIF_D * ROW_BYTES)  // 20480
#define SMEM_BYTES (LIF_NS * STAGE_BYTES)
#define NTHREADS 160

__device__ __forceinline__ uint32_t smem_u32(const void* p) {
    return (uint32_t)__cvta_generic_to_shared(p);
}

__device__ __forceinline__ void mbar_init(uint32_t bar, uint32_t count) {
    asm volatile("mbarrier.init.shared.b64 [%0], %1;" :: "r"(bar), "r"(count) : "memory");
}
__device__ __forceinline__ void mbar_arrive(uint32_t bar) {
    asm volatile("mbarrier.arrive.shared.b64 _, [%0];" :: "r"(bar) : "memory");
}
__device__ __forceinline__ void mbar_expect_tx(uint32_t bar, uint32_t bytes) {
    asm volatile("mbarrier.arrive.expect_tx.shared.b64 _, [%0], %1;"
                 :: "r"(bar), "r"(bytes) : "memory");
}
__device__ __forceinline__ void mbar_wait(uint32_t bar, uint32_t parity) {
    asm volatile(
        "{\n\t"
        ".reg .pred P;\n\t"
        "WAIT_%=:\n\t"
        "mbarrier.try_wait.parity.acquire.cta.shared::cta.b64 P, [%0], %1, 0x989680;\n\t"
        "@!P bra WAIT_%=;\n\t"
        "}"
        :: "r"(bar), "r"(parity) : "memory");
}
// TMA bulk g2s with evict_first L2 policy (single-use stream).
__device__ __forceinline__ void bulk_g2s_ef(uint32_t dst, const void* src,
                                            uint32_t bytes, uint32_t bar,
                                            uint64_t pol) {
    asm volatile(
        "cp.async.bulk.shared::cta.global.mbarrier::complete_tx::bytes.L2::cache_hint"
        " [%0], [%1], %2, [%3], %4;"
        :: "r"(dst), "l"(src), "r"(bytes), "r"(bar), "l"(pol) : "memory");
}

__global__ __launch_bounds__(NTHREADS) void lif_kernel(
    const float* __restrict__ x,
    const float* __restrict__ w_input_p,
    const float* __restrict__ w_leak_p,
    float* __restrict__ out)
{
    extern __shared__ float sdata[];                    // LIF_NS stages of [D][512] floats
    __shared__ __align__(8) uint64_t mbar[2 * LIF_NS];  // full[0..NS), empty[0..NS)

    const int tid = threadIdx.x;
    const uint32_t sbase  = smem_u32(sdata);
    const uint32_t full0  = smem_u32(&mbar[0]);
    const uint32_t empty0 = smem_u32(&mbar[LIF_NS]);

    if (tid == 0) {
        #pragma unroll
        for (int s = 0; s < LIF_NS; s++) {
            mbar_init(full0  + 8u * s, 1);    // producer expect_tx arrival
            mbar_init(empty0 + 8u * s, 128);  // all compute threads arrive
        }
    }
    __syncthreads();

    const int blk  = blockIdx.x;       // 0..127
    const int b    = blk >> 1;
    const int half = blk & 1;
    const size_t gbase = (size_t)b * LIF_T * LIF_C + (size_t)half * LIF_HALF;

    if (tid >= 128) {
        // ---------------- producer (one thread drives TMA) ----------------
        if (tid != 128) return;
        uint64_t pol;
        asm volatile("createpolicy.fractional.L2::evict_first.b64 %0, 1.0;" : "=l"(pol));
        const char* src0 = (const char*)(x + gbase);
        int ph = 1;                    // empty barriers: first pass must not block
        #pragma unroll 1
        for (int k = 0; k < LIF_NCHUNK; k++) {
            const int s = k % LIF_NS;
            mbar_wait(empty0 + 8u * s, (uint32_t)ph);
            mbar_expect_tx(full0 + 8u * s, STAGE_BYTES);
            const char* src = src0 + (size_t)k * LIF_D * LIF_C * 4;
            #pragma unroll
            for (int j = 0; j < LIF_D; j++)
                bulk_g2s_ef(sbase + (uint32_t)(s * LIF_D + j) * ROW_BYTES,
                            src + (size_t)j * LIF_C * 4,
                            ROW_BYTES, full0 + 8u * s, pol);
            if (s == LIF_NS - 1) ph ^= 1;
        }
        return;
    }

    // ---------------- compute threads (128, float4 each) ----------------
    const float wi   = *w_input_p;
    const float keep = 1.0f - *w_leak_p;

    float* orow = out + gbase;
    float Vm0 = 0.0f, Vm1 = 0.0f, Vm2 = 0.0f, Vm3 = 0.0f;
    int ph = 0;

    #pragma unroll 1
    for (int k = 0; k < LIF_NCHUNK; k++) {
        const int s = k % LIF_NS;
        mbar_wait(full0 + 8u * s, (uint32_t)ph);

        const float4* srow = (const float4*)(sdata + (size_t)s * LIF_D * LIF_HALF) + tid;
        #pragma unroll
        for (int j = 0; j < LIF_D; j++) {
            const float4 xv = srow[(size_t)j * (LIF_HALF / 4)];
            const float vk0 = (Vm0 < 1.0f) ? Vm0 : 0.0f;   // Vm * step(1-Vm)
            const float vk1 = (Vm1 < 1.0f) ? Vm1 : 0.0f;
            const float vk2 = (Vm2 < 1.0f) ? Vm2 : 0.0f;
            const float vk3 = (Vm3 < 1.0f) ? Vm3 : 0.0f;
            Vm0 = fmaxf(fmaf(keep, vk0, wi * xv.x), 0.0f);
            Vm1 = fmaxf(fmaf(keep, vk1, wi * xv.y), 0.0f);
            Vm2 = fmaxf(fmaf(keep, vk2, wi * xv.z), 0.0f);
            Vm3 = fmaxf(fmaf(keep, vk3, wi * xv.w), 0.0f);
            float4 sp;
            sp.x = (Vm0 > 1.0f) ? 1.0f : 0.0f;
            sp.y = (Vm1 > 1.0f) ? 1.0f : 0.0f;
            sp.z = (Vm2 > 1.0f) ? 1.0f : 0.0f;
            sp.w = (Vm3 > 1.0f) ? 1.0f : 0.0f;
            // Evict-first store: drain to DRAM promptly, in written order.
            __stcs((float4*)(orow + (size_t)(k * LIF_D + j) * LIF_C + tid * 4), sp);
        }

        mbar_arrive(empty0 + 8u * s);
        if (s == LIF_NS - 1) ph ^= 1;
    }
}

extern "C" void kernel_launch(void* const* d_in, const int* in_sizes, int n_in,
                              void* d_out, int out_size) {
    const float* x        = (const float*)d_in[0];
    const float* w_input  = (const float*)d_in[1];
    const float* w_leak   = (const float*)d_in[2];
    float* out            = (float*)d_out;

    cudaFuncSetAttribute(lif_kernel,
                         cudaFuncAttributeMaxDynamicSharedMemorySize, SMEM_BYTES);

    lif_kernel<<<LIF_B * 2, NTHREADS, SMEM_BYTES>>>(x, w_input, w_leak, out);
}